// round 17
// baseline (speedup 1.0000x reference)
#include <cuda_runtime.h>
#include <cstdint>

// ---------------------------------------------------------------------------
// Problem constants: x [B=4, V=2, L=8192, D=768], H=12 heads, hd=64, W=512.
// Bench lowers PTX at .target sm_103 (no 'a') — tcgen05/TMEM unavailable.
// Tensor cores via mma.sync m16n8k8 tf32 (verified R12-R14, RZ fast path).
// R15: tgemm 3-stage cp.async pipeline, single __syncthreads per K-iter.
// ---------------------------------------------------------------------------
#define DMODEL 768
#define NROWS_TOTAL 65536
#define QKV_SZ 25165824ull      // 32768 * 768

__device__ float g_y [(size_t)NROWS_TOTAL * DMODEL];
__device__ float g_qkv[6 * QKV_SZ];
__device__ float g_o  [2 * QKV_SZ];
__device__ float g_x2 [(size_t)NROWS_TOTAL * DMODEL];
__device__ float g_h  [(size_t)NROWS_TOTAL * 3072];

__device__ __forceinline__ size_t rowOff(int m, int view, int roll) {
    if (view == -1) return (size_t)m;
    if (view == -2) return (size_t)((m & ~8191) | ((m + roll) & 8191));
    int b = m >> 13;
    int l = (m + roll) & 8191;
    return (size_t)((((b << 1) + view) << 13) + l);
}

// ------------------------- PTX helpers -------------------------------------
__device__ __forceinline__ uint32_t smem_u32(const void* p) {
    uint32_t a;
    asm("{ .reg .u64 t; cvta.to.shared.u64 t, %1; cvt.u32.u64 %0, t; }"
        : "=r"(a) : "l"(p));
    return a;
}
__device__ __forceinline__ void cp_async16(uint32_t s, const float* g) {
    asm volatile("cp.async.cg.shared.global [%0], [%1], 16;\n"
                 :: "r"(s), "l"(__cvta_generic_to_global(g)) : "memory");
}
#define CP_COMMIT() asm volatile("cp.async.commit_group;\n" ::: "memory")
#define CP_WAIT(n)  asm volatile("cp.async.wait_group %0;\n" :: "n"(n) : "memory")

// RZ fast path: tf32 mma reads only the tf32-significant bits of the register.
__device__ __forceinline__ uint32_t f2tf(float f) {
    return __float_as_uint(f);
}
__device__ __forceinline__ void mma_tf32(float* c, const uint32_t* a, const uint32_t* b) {
    asm volatile(
        "mma.sync.aligned.m16n8k8.row.col.f32.tf32.tf32.f32 "
        "{%0,%1,%2,%3}, {%4,%5,%6,%7}, {%8,%9}, {%0,%1,%2,%3};"
        : "+f"(c[0]), "+f"(c[1]), "+f"(c[2]), "+f"(c[3])
        : "r"(a[0]), "r"(a[1]), "r"(a[2]), "r"(a[3]), "r"(b[0]), "r"(b[1]));
}

// ---------------------------------------------------------------------------
// tf32 mma.sync GEMM: C = A*W^T (+bias, gelu, resid)
// 128x128 block tile, 256 thr (8 warps, 2x4), warp tile 64x32.
// 3-stage cp.async pipeline, 1 barrier per 32-float K chunk.
// ---------------------------------------------------------------------------
__global__ void __launch_bounds__(256)
tgemm_kernel(const float* __restrict__ A, const float* __restrict__ W,
             const float* __restrict__ bias, float* __restrict__ C,
             const float* __restrict__ resid,
             int K, int N, int Aview, int ArollSign, int Cview, int actGelu,
             const int* __restrict__ idxp)
{
    extern __shared__ __align__(16) float smemf[];   // 3 stages * (A+B)128*36
    uint32_t sb = smem_u32(smemf);

    int tid  = threadIdx.x;
    int wid  = tid >> 5;
    int lane = tid & 31;
    int bn = blockIdx.x, bm = blockIdx.y;

    int shf = idxp ? ((idxp[0] & 1) << 8) : 0;
    int roll = 0;
    if (ArollSign > 0) roll = shf;
    else if (ArollSign < 0) roll = (8192 - shf) & 8191;

    int r0 = tid >> 3;
    int kq = tid & 7;
    const float* aptr[4];
    const float* bptr[4];
    #pragma unroll
    for (int i = 0; i < 4; i++) {
        int row = r0 + 32 * i;
        aptr[i] = A + rowOff(bm * 128 + row, Aview, roll) * (size_t)K + (kq << 2);
        bptr[i] = W + (size_t)(bn * 128 + row) * K + (kq << 2);
    }
    uint32_t dstA = (uint32_t)(r0 * 144 + kq * 16);

    auto fill = [&](int st, int kt) {
        uint32_t base = sb + (uint32_t)st * 36864u;
        int ko = kt << 5;
        #pragma unroll
        for (int i = 0; i < 4; i++) {
            cp_async16(base + dstA + (uint32_t)(i * 4608),           aptr[i] + ko);
            cp_async16(base + 18432u + dstA + (uint32_t)(i * 4608),  bptr[i] + ko);
        }
    };

    int warpM = wid & 1, warpN = wid >> 1;
    int m_base = warpM * 64, n_base = warpN * 32;
    int g = lane >> 2, q = lane & 3;

    float acc[4][4][4];
    #pragma unroll
    for (int tm = 0; tm < 4; tm++)
        #pragma unroll
        for (int tn = 0; tn < 4; tn++)
            #pragma unroll
            for (int e = 0; e < 4; e++) acc[tm][tn][e] = 0.f;

    int KT = K >> 5;      // >= 24 for all shapes here
    fill(0, 0); CP_COMMIT();
    fill(1, 1); CP_COMMIT();
    fill(2, 2); CP_COMMIT();

    int st = 0;           // stage = kt % 3
    for (int kt = 0; kt < KT; kt++) {
        if (kt + 1 < KT) CP_WAIT(1); else CP_WAIT(0);
        __syncthreads();
        // buffer (kt-1)%3 freed by the barrier; refill it with kt+2
        if (kt >= 1 && kt + 2 < KT) {
            int fs = st - 1; if (fs < 0) fs = 2;   // (kt+2)%3 == (kt-1)%3
            fill(fs, kt + 2);
            CP_COMMIT();
        }

        const float* Ab = smemf + st * 9216;
        const float* Bb = Ab + 4608;

        #pragma unroll
        for (int kk = 0; kk < 32; kk += 8) {
            uint32_t af[4][4], bf[4][2];
            #pragma unroll
            for (int tm = 0; tm < 4; tm++) {
                int r = m_base + tm * 16 + g;
                af[tm][0] = f2tf(Ab[r * 36 + kk + q]);
                af[tm][1] = f2tf(Ab[(r + 8) * 36 + kk + q]);
                af[tm][2] = f2tf(Ab[r * 36 + kk + 4 + q]);
                af[tm][3] = f2tf(Ab[(r + 8) * 36 + kk + 4 + q]);
            }
            #pragma unroll
            for (int tn = 0; tn < 4; tn++) {
                int c = n_base + tn * 8 + g;
                bf[tn][0] = f2tf(Bb[c * 36 + kk + q]);
                bf[tn][1] = f2tf(Bb[c * 36 + kk + 4 + q]);
            }
            #pragma unroll
            for (int tm = 0; tm < 4; tm++)
                #pragma unroll
                for (int tn = 0; tn < 4; tn++)
                    mma_tf32(acc[tm][tn], af[tm], bf[tn]);
        }
        if (++st == 3) st = 0;
    }

    #pragma unroll
    for (int tm = 0; tm < 4; tm++) {
        int mr = bm * 128 + m_base + tm * 16 + g;
        size_t cb0 = rowOff(mr,     Cview, 0) * (size_t)N;
        size_t cb1 = rowOff(mr + 8, Cview, 0) * (size_t)N;
        #pragma unroll
        for (int tn = 0; tn < 4; tn++) {
            int col = bn * 128 + n_base + tn * 8 + 2 * q;
            float2 bv = *(const float2*)(bias + col);
            float2 v0, v1;
            v0.x = acc[tm][tn][0] + bv.x;  v0.y = acc[tm][tn][1] + bv.y;
            v1.x = acc[tm][tn][2] + bv.x;  v1.y = acc[tm][tn][3] + bv.y;
            if (actGelu) {
                v0.x = v0.x / (1.f + __expf(-1.702f * v0.x));
                v0.y = v0.y / (1.f + __expf(-1.702f * v0.y));
                v1.x = v1.x / (1.f + __expf(-1.702f * v1.x));
                v1.y = v1.y / (1.f + __expf(-1.702f * v1.y));
            }
            if (resid) {
                float2 r0v = *(const float2*)(resid + cb0 + col);
                float2 r1v = *(const float2*)(resid + cb1 + col);
                v0.x += r0v.x; v0.y += r0v.y;
                v1.x += r1v.x; v1.y += r1v.y;
            }
            *(float2*)(C + cb0 + col) = v0;
            *(float2*)(C + cb1 + col) = v1;
        }
    }
}

// ---------------------------------------------------------------------------
// LayerNorm (R1-verified)
// ---------------------------------------------------------------------------
__global__ void __launch_bounds__(192)
ln_kernel(const float* __restrict__ x, const float* __restrict__ g,
          const float* __restrict__ b, float* __restrict__ y)
{
    __shared__ float sh[8];
    int row = blockIdx.x;
    int t = threadIdx.x;
    const float4* xr = (const float4*)(x + (size_t)row * DMODEL);
    float4 v = xr[t];

    float s = v.x + v.y + v.z + v.w;
    #pragma unroll
    for (int o = 16; o; o >>= 1) s += __shfl_xor_sync(0xffffffffu, s, o);
    if ((t & 31) == 0) sh[t >> 5] = s;
    __syncthreads();
    s = sh[0] + sh[1] + sh[2] + sh[3] + sh[4] + sh[5];
    float mean = s * (1.0f / 768.0f);

    float dx = v.x - mean, dy = v.y - mean, dz = v.z - mean, dw = v.w - mean;
    float q = dx * dx + dy * dy + dz * dz + dw * dw;
    __syncthreads();
    #pragma unroll
    for (int o = 16; o; o >>= 1) q += __shfl_xor_sync(0xffffffffu, q, o);
    if ((t & 31) == 0) sh[t >> 5] = q;
    __syncthreads();
    q = sh[0] + sh[1] + sh[2] + sh[3] + sh[4] + sh[5];
    float rs = rsqrtf(q * (1.0f / 768.0f) + 1e-5f);

    float4 gg = ((const float4*)g)[t];
    float4 bb = ((const float4*)b)[t];
    float4 o4;
    o4.x = dx * rs * gg.x + bb.x;
    o4.y = dy * rs * gg.y + bb.y;
    o4.z = dz * rs * gg.z + bb.z;
    o4.w = dw * rs * gg.w + bb.w;
    ((float4*)(y + (size_t)row * DMODEL))[t] = o4;
}

// ---------------------------------------------------------------------------
// Flash attention on mma.sync tensor cores (R13/R14-verified)
// ---------------------------------------------------------------------------
#define ALD 68

__global__ void __launch_bounds__(128)
attn_kernel()
{
    extern __shared__ __align__(16) float smx[];
    float* Qs  = smx;              // [64][ALD]
    float* KVs = Qs + 64 * ALD;    // [64][ALD]: K rows, then V^T [d][key]
    float* Ps  = KVs + 64 * ALD;   // [64][ALD]

    int t  = threadIdx.x;
    int wid = t >> 5, lane = t & 31;
    int g = lane >> 2, q = lane & 3;
    int rbase = wid * 16;

    int qt = blockIdx.x;
    int hd = blockIdx.y;
    int z  = blockIdx.z;
    int mod = z >> 6;
    int b   = (z >> 4) & 3;
    int w   = z & 15;

    const float* Qb = g_qkv + (size_t)(0 + mod) * QKV_SZ;
    const float* Kb = g_qkv + (size_t)(2 + mod) * QKV_SZ;
    const float* Vb = g_qkv + (size_t)(4 + mod) * QKV_SZ;
    float* Ob = g_o + (size_t)mod * QKV_SZ;

    int winTok = b * 8192 + w * 512;
    int qTok = winTok + qt * 64;
    int hOff = hd * 64;

    for (int idx = t; idx < 1024; idx += 128) {
        int rr = idx >> 4;
        int c4 = (idx & 15) << 2;
        float4 v = *(const float4*)(Qb + (size_t)(qTok + rr) * 768 + hOff + c4);
        v.x *= 0.125f; v.y *= 0.125f; v.z *= 0.125f; v.w *= 0.125f;
        *(float4*)&Qs[rr * ALD + c4] = v;
    }

    float Oa[8][4];
    #pragma unroll
    for (int dt = 0; dt < 8; dt++)
        #pragma unroll
        for (int e = 0; e < 4; e++) Oa[dt][e] = 0.f;
    float m0 = -1e30f, m1 = -1e30f, l0 = 0.f, l1 = 0.f;

    for (int kt = 0; kt < 8; kt++) {
        int kTok = winTok + kt * 64;
        for (int idx = t; idx < 1024; idx += 128) {
            int rr = idx >> 4;
            int c4 = (idx & 15) << 2;
            float4 v = *(const float4*)(Kb + (size_t)(kTok + rr) * 768 + hOff + c4);
            *(float4*)&KVs[rr * ALD + c4] = v;
        }
        __syncthreads();

        float S[8][4];
        #pragma unroll
        for (int nt = 0; nt < 8; nt++)
            #pragma unroll
            for (int e = 0; e < 4; e++) S[nt][e] = 0.f;

        #pragma unroll
        for (int kk = 0; kk < 64; kk += 8) {
            uint32_t af[4];
            af[0] = f2tf(Qs[(rbase + g) * ALD + kk + q]);
            af[1] = f2tf(Qs[(rbase + g + 8) * ALD + kk + q]);
            af[2] = f2tf(Qs[(rbase + g) * ALD + kk + 4 + q]);
            af[3] = f2tf(Qs[(rbase + g + 8) * ALD + kk + 4 + q]);
            #pragma unroll
            for (int nt = 0; nt < 8; nt++) {
                uint32_t bf[2];
                bf[0] = f2tf(KVs[(nt * 8 + g) * ALD + kk + q]);
                bf[1] = f2tf(KVs[(nt * 8 + g) * ALD + kk + 4 + q]);
                mma_tf32(S[nt], af, bf);
            }
        }
        __syncthreads();

        float mx0 = -1e30f, mx1 = -1e30f;
        #pragma unroll
        for (int nt = 0; nt < 8; nt++) {
            mx0 = fmaxf(mx0, fmaxf(S[nt][0], S[nt][1]));
            mx1 = fmaxf(mx1, fmaxf(S[nt][2], S[nt][3]));
        }
        mx0 = fmaxf(mx0, __shfl_xor_sync(0xffffffffu, mx0, 1));
        mx0 = fmaxf(mx0, __shfl_xor_sync(0xffffffffu, mx0, 2));
        mx1 = fmaxf(mx1, __shfl_xor_sync(0xffffffffu, mx1, 1));
        mx1 = fmaxf(mx1, __shfl_xor_sync(0xffffffffu, mx1, 2));

        float mn0 = fmaxf(m0, mx0), mn1 = fmaxf(m1, mx1);
        float al0 = __expf(m0 - mn0), al1 = __expf(m1 - mn1);
        float sum0 = 0.f, sum1 = 0.f;
        #pragma unroll
        for (int nt = 0; nt < 8; nt++) {
            float p00 = __expf(S[nt][0] - mn0);
            float p01 = __expf(S[nt][1] - mn0);
            float p10 = __expf(S[nt][2] - mn1);
            float p11 = __expf(S[nt][3] - mn1);
            sum0 += p00 + p01;
            sum1 += p10 + p11;
            float2 w0 = make_float2(p00, p01);
            float2 w1 = make_float2(p10, p11);
            *(float2*)&Ps[(rbase + g) * ALD + nt * 8 + 2 * q] = w0;
            *(float2*)&Ps[(rbase + g + 8) * ALD + nt * 8 + 2 * q] = w1;
        }
        sum0 += __shfl_xor_sync(0xffffffffu, sum0, 1);
        sum0 += __shfl_xor_sync(0xffffffffu, sum0, 2);
        sum1 += __shfl_xor_sync(0xffffffffu, sum1, 1);
        sum1 += __shfl_xor_sync(0xffffffffu, sum1, 2);
        l0 = l0 * al0 + sum0;
        l1 = l1 * al1 + sum1;
        m0 = mn0; m1 = mn1;
        #pragma unroll
        for (int dt = 0; dt < 8; dt++) {
            Oa[dt][0] *= al0; Oa[dt][1] *= al0;
            Oa[dt][2] *= al1; Oa[dt][3] *= al1;
        }

        for (int idx = t; idx < 1024; idx += 128) {
            int key = idx >> 4;
            int d4 = (idx & 15) << 2;
            float4 v = *(const float4*)(Vb + (size_t)(kTok + key) * 768 + hOff + d4);
            KVs[(d4 + 0) * ALD + key] = v.x;
            KVs[(d4 + 1) * ALD + key] = v.y;
            KVs[(d4 + 2) * ALD + key] = v.z;
            KVs[(d4 + 3) * ALD + key] = v.w;
        }
        __syncthreads();

        #pragma unroll
        for (int kk = 0; kk < 64; kk += 8) {
            uint32_t af[4];
            af[0] = f2tf(Ps[(rbase + g) * ALD + kk + q]);
            af[1] = f2tf(Ps[(rbase + g + 8) * ALD + kk + q]);
            af[2] = f2tf(Ps[(rbase + g) * ALD + kk + 4 + q]);
            af[3] = f2tf(Ps[(rbase + g + 8) * ALD + kk + 4 + q]);
            #pragma unroll
            for (int dt = 0; dt < 8; dt++) {
                uint32_t bf[2];
                bf[0] = f2tf(KVs[(dt * 8 + g) * ALD + kk + q]);
                bf[1] = f2tf(KVs[(dt * 8 + g) * ALD + kk + 4 + q]);
                mma_tf32(Oa[dt], af, bf);
            }
        }
        __syncthreads();
    }

    float inv0 = 1.f / l0, inv1 = 1.f / l1;
    float* orow0 = Ob + (size_t)(qTok + rbase + g) * 768 + hOff;
    float* orow1 = Ob + (size_t)(qTok + rbase + g + 8) * 768 + hOff;
    #pragma unroll
    for (int dt = 0; dt < 8; dt++) {
        int col = dt * 8 + 2 * q;
        *(float2*)(orow0 + col) = make_float2(Oa[dt][0] * inv0, Oa[dt][1] * inv0);
        *(float2*)(orow1 + col) = make_float2(Oa[dt][2] * inv1, Oa[dt][3] * inv1);
    }
}

// ---------------------------------------------------------------------------
// Launch sequence
// ---------------------------------------------------------------------------
extern "C" void kernel_launch(void* const* d_in, const int* in_sizes, int n_in,
                              void* d_out, int out_size)
{
    (void)in_sizes; (void)out_size;
    const float* x       = (const float*)d_in[0];
    const float* ln1_g   = (const float*)d_in[1];
    const float* ln1_b   = (const float*)d_in[2];
    const float* ln2_g   = (const float*)d_in[3];
    const float* ln2_b   = (const float*)d_in[4];
    const float* a1_wqkv = (const float*)d_in[5];
    const float* a1_bqkv = (const float*)d_in[6];
    const float* a1_wo   = (const float*)d_in[7];
    const float* a1_bo   = (const float*)d_in[8];
    const float* a2_wqkv = (const float*)d_in[9];
    const float* a2_bqkv = (const float*)d_in[10];
    const float* a2_wo   = (const float*)d_in[11];
    const float* a2_bo   = (const float*)d_in[12];
    const float* fc_w    = (const float*)d_in[13];
    const float* fc_b    = (const float*)d_in[14];
    const float* proj_w  = (const float*)d_in[15];
    const float* proj_b  = (const float*)d_in[16];
    const int*   idxp    = (n_in > 17) ? (const int*)d_in[17] : nullptr;
    float* out = (float*)d_out;

    float *y, *qkv, *o, *x2, *h;
    cudaGetSymbolAddress((void**)&y,  g_y);
    cudaGetSymbolAddress((void**)&qkv, g_qkv);
    cudaGetSymbolAddress((void**)&o,  g_o);
    cudaGetSymbolAddress((void**)&x2, g_x2);
    cudaGetSymbolAddress((void**)&h,  g_h);

    const int AS = 3 * 64 * ALD * 4;   // 52224 B
    const int GS = 3 * 36864;          // 110592 B (3-stage pipeline)
    cudaFuncSetAttribute(attn_kernel,
                         cudaFuncAttributeMaxDynamicSharedMemorySize, AS);
    cudaFuncSetAttribute(tgemm_kernel,
                         cudaFuncAttributeMaxDynamicSharedMemorySize, GS);

    const size_t SZ = QKV_SZ;
    const int WQ = 589824;     // 768*768

    // 1) y = LN1(x)
    ln_kernel<<<65536, 192>>>(x, ln1_g, ln1_b, y);

    // 2) QKV projections (compact per-view outputs)
    tgemm_kernel<<<dim3(6, 256), 256, GS>>>(y, a1_wqkv,          a1_bqkv,        qkv + 0 * SZ, nullptr, 768, 768,  0,  0, -1, 0, idxp);
    tgemm_kernel<<<dim3(6, 256), 256, GS>>>(y, a2_wqkv,          a2_bqkv,        qkv + 1 * SZ, nullptr, 768, 768,  1,  0, -1, 0, idxp);
    tgemm_kernel<<<dim3(6, 256), 256, GS>>>(y, a1_wqkv + WQ,     a1_bqkv + 768,  qkv + 2 * SZ, nullptr, 768, 768,  1,  0, -1, 0, idxp);
    tgemm_kernel<<<dim3(6, 256), 256, GS>>>(y, a2_wqkv + WQ,     a2_bqkv + 768,  qkv + 3 * SZ, nullptr, 768, 768,  0,  0, -1, 0, idxp);
    tgemm_kernel<<<dim3(6, 256), 256, GS>>>(x, a1_wqkv + 2 * WQ, a1_bqkv + 1536, qkv + 4 * SZ, nullptr, 768, 768,  0, -1, -1, 0, idxp);
    tgemm_kernel<<<dim3(6, 256), 256, GS>>>(x, a2_wqkv + 2 * WQ, a2_bqkv + 1536, qkv + 5 * SZ, nullptr, 768, 768,  1, -1, -1, 0, idxp);

    // 3) windowed flash attention (tensor cores)
    attn_kernel<<<dim3(8, 12, 128), 128, AS>>>();

    // 4) out-proj + un-roll + residual
    tgemm_kernel<<<dim3(6, 256), 256, GS>>>(o,      a1_wo, a1_bo, x2, x, 768, 768, -2, +1, 0, 0, idxp);
    tgemm_kernel<<<dim3(6, 256), 256, GS>>>(o + SZ, a2_wo, a2_bo, x2, x, 768, 768, -2, +1, 1, 0, idxp);

    // 5) y = LN2(x2)
    ln_kernel<<<65536, 192>>>(x2, ln2_g, ln2_b, y);

    // 6) h = gelu(y @ fc_w.T + fc_b)
    tgemm_kernel<<<dim3(24, 512), 256, GS>>>(y, fc_w, fc_b, h, nullptr, 768, 3072, -1, 0, -1, 1, idxp);

    // 7) out = x2 + h @ proj_w.T + proj_b
    tgemm_kernel<<<dim3(6, 512), 256, GS>>>(h, proj_w, proj_b, out, x2, 3072, 768, -1, 0, -1, 0, idxp);
}